// round 13
// baseline (speedup 1.0000x reference)
#include <cuda_runtime.h>
#include <cuda_bf16.h>
#include <math.h>
#include <stdint.h>

// Problem constants
#define BB 64
#define CC 2048
#define MM 64      // 8*8 pooled positions
#define PP 1000    // 100 classes * 10 protos
#define EPS_TIE 3e-5f

// Output segment offsets (floats), tuple order:
// out, contrib, sim_r, cosvalue_u, cosdist_u, maxfs_u, argmaxdist
#define OFF_OUT      0ull
#define OFF_CONTRIB  6400ull
#define OFF_SIM      70400ull
#define OFF_COSV     134400ull
#define OFF_COSD     4230400ull
#define OFF_MAXFS    8326400ull
#define OFF_ARGMAX   139398400ull

// Scratch (device globals: allocation-free rule)
static __device__ float g_fNraw[(size_t)BB * MM * CC];     // pooled, [b][m][c] (unnormalized)
static __device__ float g_protoT[(size_t)1024 * CC];       // raw proto, p-major
// bf16 fragment-packed operands for m16n8k16:
// A: [mt(256)][kq(128)][lane(32)][4 u32], B: [nt(128)][kq(128)][lane(32)][2 u32]
static __device__ uint32_t g_Ah[(size_t)256 * 128 * 32 * 4];
static __device__ uint32_t g_Al[(size_t)256 * 128 * 32 * 4];
static __device__ uint32_t g_Bh[(size_t)128 * 128 * 32 * 2];
static __device__ uint32_t g_Bl[(size_t)128 * 128 * 32 * 2];
static __device__ float g_cpart2[16][1024];                // proto sumsq partials [chunk][p]
static __device__ float g_inv_norm[BB * MM];
static __device__ float g_row_scale[BB * MM];

__device__ __forceinline__ uint32_t smem_u32(const void* p) {
    uint32_t a;
    asm("{ .reg .u64 t; cvta.to.shared.u64 t, %1; cvt.u32.u64 %0, t; }" : "=r"(a) : "l"(p));
    return a;
}
__device__ __forceinline__ float bfh(float v) {
    return __bfloat162float(__float2bfloat16_rn(v));
}
__device__ __forceinline__ uint32_t pack_bf(float lo, float hi) {
    uint32_t r;
    asm("cvt.rn.bf16x2.f32 %0, %1, %2;" : "=r"(r) : "f"(hi), "f"(lo));
    return r;
}
#define CP_ASYNC16(sm, gp) \
    asm volatile("cp.async.cg.shared.global [%0], [%1], 16;" :: "r"(sm), "l"(gp))
#define CP_COMMIT() asm volatile("cp.async.commit_group;" ::: "memory")
#define CP_WAIT2()  asm volatile("cp.async.wait_group 2;" ::: "memory")
#define CP_WAIT0()  asm volatile("cp.async.wait_group 0;" ::: "memory")
#define MMA_BF16(d, a, b) \
    asm volatile("mma.sync.aligned.m16n8k16.row.col.f32.bf16.bf16.f32 " \
        "{%0,%1,%2,%3}, {%4,%5,%6,%7}, {%8,%9}, {%0,%1,%2,%3};" \
        : "+f"((d)[0]), "+f"((d)[1]), "+f"((d)[2]), "+f"((d)[3]) \
        : "r"((a)[0]), "r"((a)[1]), "r"((a)[2]), "r"((a)[3]), \
          "r"((b)[0]), "r"((b)[1]))

// ---------------------------------------------------------------------------
// 1) Fused pool (16x16 -> 8x8) + transposed fNraw write + bf16 A-frag pack.
// ---------------------------------------------------------------------------
__global__ void poolpack_kernel(const float* __restrict__ x) {
    __shared__ float sp[16][72];
    int t = threadIdx.x;
    int kq = blockIdx.x;    // 0..127
    int b = blockIdx.y;     // 0..63
#pragma unroll
    for (int i = 0; i < 2; ++i) {
        int u = t + i * 256;            // 0..511
        int cl = u >> 5;                 // 0..15
        int m2 = (u & 31) * 2;
        int c = kq * 16 + cl;
        int ii = m2 >> 3, j = m2 & 7;    // j even
        const float* xp = x + ((size_t)(b * CC + c)) * 256;
        float4 r0 = *(const float4*)&xp[(2 * ii) * 16 + 2 * j];
        float4 r1 = *(const float4*)&xp[(2 * ii + 1) * 16 + 2 * j];
        sp[cl][m2]     = 0.25f * ((r0.x + r0.y) + (r1.x + r1.y));
        sp[cl][m2 + 1] = 0.25f * ((r0.z + r0.w) + (r1.z + r1.w));
    }
    __syncthreads();
    // transposed write: fNraw[b][m][kq*16 + c]
    {
        int m = t >> 2, c4 = (t & 3) * 4;
        float4 o = make_float4(sp[c4][m], sp[c4 + 1][m], sp[c4 + 2][m], sp[c4 + 3][m]);
        *(float4*)&g_fNraw[((size_t)(b * 64 + m)) * CC + kq * 16 + c4] = o;
    }
    // A fragment pack (hi/lo split)
    int h = t >> 7;        // 0: hi, 1: lo
    int q = t & 127;
    int f = q >> 5, lane = q & 31;
    int g = lane >> 2, tig = lane & 3;
    int m = f * 16 + g;
    float vals[8];
    vals[0] = sp[2 * tig][m];       vals[1] = sp[2 * tig + 1][m];
    vals[2] = sp[2 * tig][m + 8];   vals[3] = sp[2 * tig + 1][m + 8];
    vals[4] = sp[2 * tig + 8][m];     vals[5] = sp[2 * tig + 9][m];
    vals[6] = sp[2 * tig + 8][m + 8]; vals[7] = sp[2 * tig + 9][m + 8];
    uint32_t out[4];
#pragma unroll
    for (int r = 0; r < 4; ++r) {
        float e = vals[2 * r], o = vals[2 * r + 1];
        if (h == 0) out[r] = pack_bf(e, o);
        else        out[r] = pack_bf(e - bfh(e), o - bfh(o));
    }
    size_t idx = (((size_t)(b * 4 + f) * 128 + kq) * 32 + lane) * 4;
    if (h == 0) *(uint4*)&g_Ah[idx] = make_uint4(out[0], out[1], out[2], out[3]);
    else        *(uint4*)&g_Al[idx] = make_uint4(out[0], out[1], out[2], out[3]);
}

// ---------------------------------------------------------------------------
// 2) B fragment pack (bf16 split) + raw protoT + fused column-sumsq partials.
// ---------------------------------------------------------------------------
__global__ void bpackcol_kernel(const float* __restrict__ proto) {
    __shared__ float sq[8][8];
    int t = threadIdx.x;
    int gt = blockIdx.x * 256 + t;             // 0 .. 524287
    int lane = gt & 31;
    int frag = gt >> 5;                         // nt*128 + kq
    int kq = frag & 127, nt = frag >> 7;
    int g = lane >> 2, tig = lane & 3;
    int p = nt * 8 + g;
    int kb = kq * 16;
    float v0 = 0.f, v1 = 0.f, v2 = 0.f, v3 = 0.f;
    if (p < PP) {
        v0 = proto[(size_t)(kb + 2 * tig) * PP + p];
        v1 = proto[(size_t)(kb + 2 * tig + 1) * PP + p];
        v2 = proto[(size_t)(kb + 2 * tig + 8) * PP + p];
        v3 = proto[(size_t)(kb + 2 * tig + 9) * PP + p];
    }
    uint32_t b0h = pack_bf(v0, v1), b1h = pack_bf(v2, v3);
    uint32_t b0l = pack_bf(v0 - bfh(v0), v1 - bfh(v1));
    uint32_t b1l = pack_bf(v2 - bfh(v2), v3 - bfh(v3));
    size_t o = (size_t)frag * 64 + lane * 2;
    *(uint2*)&g_Bh[o] = make_uint2(b0h, b1h);
    *(uint2*)&g_Bl[o] = make_uint2(b0l, b1l);
    if (p < PP) {
        g_protoT[(size_t)p * CC + kb + 2 * tig]     = v0;
        g_protoT[(size_t)p * CC + kb + 2 * tig + 1] = v1;
        g_protoT[(size_t)p * CC + kb + 2 * tig + 8] = v2;
        g_protoT[(size_t)p * CC + kb + 2 * tig + 9] = v3;
    }
    float ss = v0 * v0 + v1 * v1 + v2 * v2 + v3 * v3;
    ss += __shfl_xor_sync(0xffffffffu, ss, 1);
    ss += __shfl_xor_sync(0xffffffffu, ss, 2);
    int wloc = t >> 5;
    if (tig == 0) sq[wloc][g] = ss;
    __syncthreads();
    if (t < 8) {
        float s = 0.f;
#pragma unroll
        for (int w2 = 0; w2 < 8; ++w2) s += sq[w2][t];
        int ntb = (blockIdx.x * 8) >> 7;
        int chunk = blockIdx.x & 15;
        g_cpart2[chunk][ntb * 8 + t] = s;
    }
}

// ---------------------------------------------------------------------------
// 3) Row norms: coalesced over fNraw rows
// ---------------------------------------------------------------------------
__global__ void norm_kernel() {
    int b = blockIdx.x;
    int w = threadIdx.x >> 5, lane = threadIdx.x & 31;
#pragma unroll
    for (int i = 0; i < 8; ++i) {
        int m = w * 8 + i;
        const float4* row = (const float4*)(g_fNraw + ((size_t)(b * 64 + m)) * CC);
        float s = 0.f;
        for (int c = lane; c < 512; c += 32) {
            float4 v = row[c];
            s += v.x * v.x + v.y * v.y + v.z * v.z + v.w * v.w;
        }
#pragma unroll
        for (int off = 16; off; off >>= 1)
            s += __shfl_xor_sync(0xffffffffu, s, off);
        if (lane == 0) {
            float s1 = sqrtf(s);
            float r1 = 1.f / fmaxf(s1, 1e-12f);
            float na = s1 * r1 + 1e-3f;
            g_inv_norm[b * 64 + m] = r1;
            g_row_scale[b * 64 + m] = r1 / na;
        }
    }
}

// ---------------------------------------------------------------------------
// 4) bf16 3-split mma.sync GEMM + fused epilogue, software-pipelined tiles:
//    grid (16,16); each CTA runs tiles by and by+16 (same p-range).
//    Tile-0 defers its 1MB maxfs write; tile-1's mainloop streams it out in
//    per-kt chunks interleaved with MMAs (DRAM idle during mainloop).
//    4-stage k32 ring, one __syncthreads per kt.
// ---------------------------------------------------------------------------
#define STAGE 24576
#define RING  (4 * STAGE)              // 98304
#define SSTR 129
#define MMA_SMEM (RING + 2304)
__global__ __launch_bounds__(256, 2) void mma_kernel(const float* __restrict__ wgt,
                                                     const float* __restrict__ wgte,
                                                     float* __restrict__ dout) {
    extern __shared__ char smem[];
    uint32_t sb = smem_u32(smem);
    float* PS = (float*)(smem + RING);
    float* s_scs      = PS;              // [64]
    float* s_srs      = PS + 64;         // [128]
    int*   s_rowsrc   = (int*)(PS + 192);   // [128]
    int*   s_pairdst  = (int*)(PS + 320);   // [128]
    float* s_rowscale = PS + 448;        // [128]

    int t = threadIdx.x;
    int lane = t & 31, w = t >> 5;
    int wm = w & 1, wn = w >> 1;
    int nt0 = blockIdx.x * 8;
    int p0 = blockIdx.x * 64;

    // one-time init: col scales + pairdst sentinel
    if (t < 64) {
        int p = p0 + t;
        float s = 0.f;
#pragma unroll
        for (int ch = 0; ch < 16; ++ch) s += g_cpart2[ch][p];
        float s1 = sqrtf(s);
        float r1 = 1.f / fmaxf(s1, 1e-12f);
        s_scs[t] = r1 / (s1 * r1 + 1e-3f);
    }
    if (t < 128) s_pairdst[t] = -1;

#pragma unroll 1
    for (int tile = 0; tile < 2; ++tile) {
        int by = blockIdx.y + tile * 16;
        int mt0 = by * 8;
        int b0 = by * 2;

        float acc[4][2][4];
#pragma unroll
        for (int i = 0; i < 4; ++i)
#pragma unroll
            for (int j = 0; j < 2; ++j)
#pragma unroll
                for (int q = 0; q < 4; ++q) acc[i][j][q] = 0.f;

        auto load_stage = [&](int sbuf, int kt) {
            uint32_t st = sb + sbuf * STAGE;
            int k0q = kt * 2;
#pragma unroll
            for (int i = 0; i < 2; ++i) {
                int q = t + i * 256;
                int frag = q >> 5, off = q & 31;
                int kq2 = frag >> 3, mtl = frag & 7;
                size_t gidx = (((size_t)(mt0 + mtl) * 128) + k0q + kq2) * 128 + off * 4;
                CP_ASYNC16(st + frag * 512 + off * 16, g_Ah + gidx);
                CP_ASYNC16(st + 8192 + frag * 512 + off * 16, g_Al + gidx);
            }
            {
                int frag = t >> 4, off = t & 15;
                int kq2 = frag >> 3, ntl = frag & 7;
                size_t gidx = (((size_t)(nt0 + ntl) * 128) + k0q + kq2) * 64 + off * 4;
                CP_ASYNC16(st + 16384 + frag * 256 + off * 16, g_Bh + gidx);
                CP_ASYNC16(st + 20480 + frag * 256 + off * 16, g_Bl + gidx);
            }
        };

        load_stage(0, 0); CP_COMMIT();
        load_stage(1, 1); CP_COMMIT();
        load_stage(2, 2); CP_COMMIT();

        for (int kt = 0; kt < 64; ++kt) {
            CP_WAIT2();
            __syncthreads();
            if (kt < 61) load_stage((kt + 3) & 3, kt + 3);
            // deferred tile-0 maxfs writes, streamed under tile-1's MMAs
            if (tile == 1) {
                int row = t >> 1;
                int dp = s_pairdst[row];
                if (dp >= 0) {
                    float r1 = s_rowscale[row];
                    int base = (t & 1) * 4;
                    const float4* src = (const float4*)g_fNraw +
                                        (size_t)s_rowsrc[row] * 512 + kt * 8 + base;
                    float4* dd = (float4*)(dout + OFF_MAXFS) +
                                 (size_t)dp * 512 + kt * 8 + base;
#pragma unroll
                    for (int j = 0; j < 4; ++j) {
                        float4 v = src[j];
                        v.x *= r1; v.y *= r1; v.z *= r1; v.w *= r1;
                        __stcs(&dd[j], v);
                    }
                }
            }
            uint32_t st = sb + (kt & 3) * STAGE;
#pragma unroll
            for (int kq2 = 0; kq2 < 2; ++kq2) {
                uint32_t bh[2][2], bl[2][2];
#pragma unroll
                for (int nt = 0; nt < 2; ++nt) {
                    uint32_t bo = st + 16384 + (uint32_t)((kq2 * 8 + wn * 2 + nt) * 32 + lane) * 8;
                    asm("ld.shared.v2.b32 {%0,%1}, [%2];"
                        : "=r"(bh[nt][0]), "=r"(bh[nt][1]) : "r"(bo));
                    asm("ld.shared.v2.b32 {%0,%1}, [%2];"
                        : "=r"(bl[nt][0]), "=r"(bl[nt][1]) : "r"(bo + 4096));
                }
#pragma unroll
                for (int mt = 0; mt < 4; ++mt) {
                    uint32_t ah[4], al[4];
                    uint32_t ao = st + (uint32_t)((kq2 * 8 + wm * 4 + mt) * 32 + lane) * 16;
                    asm("ld.shared.v4.b32 {%0,%1,%2,%3}, [%4];"
                        : "=r"(ah[0]), "=r"(ah[1]), "=r"(ah[2]), "=r"(ah[3]) : "r"(ao));
                    asm("ld.shared.v4.b32 {%0,%1,%2,%3}, [%4];"
                        : "=r"(al[0]), "=r"(al[1]), "=r"(al[2]), "=r"(al[3]) : "r"(ao + 8192));
#pragma unroll
                    for (int nt = 0; nt < 2; ++nt) {
                        MMA_BF16(acc[mt][nt], ah, bh[nt]);
                        MMA_BF16(acc[mt][nt], ah, bl[nt]);
                        MMA_BF16(acc[mt][nt], al, bh[nt]);
                    }
                }
            }
            CP_COMMIT();
        }
        CP_WAIT0();
        __syncthreads();

        // ---- epilogue ----
        float* S = (float*)smem;                  // [64][SSTR] (stage area reuse)
        if (t >= 128) s_srs[t - 128] = g_row_scale[b0 * 64 + (t - 128)];
        __syncthreads();

        int g = lane >> 2, tig = lane & 3;
#pragma unroll
        for (int mt = 0; mt < 4; ++mt) {
            int ml0 = (wm * 4 + mt) * 16 + g;
#pragma unroll
            for (int nt = 0; nt < 2; ++nt) {
                int pl = (wn * 2 + nt) * 8 + tig * 2;
                S[pl * SSTR + ml0]           = acc[mt][nt][0] * s_srs[ml0] * s_scs[pl];
                S[(pl + 1) * SSTR + ml0]     = acc[mt][nt][1] * s_srs[ml0] * s_scs[pl + 1];
                S[pl * SSTR + ml0 + 8]       = acc[mt][nt][2] * s_srs[ml0 + 8] * s_scs[pl];
                S[(pl + 1) * SSTR + ml0 + 8] = acc[mt][nt][3] * s_srs[ml0 + 8] * s_scs[pl + 1];
            }
        }
        __syncthreads();

        // per-warp: 8 p-columns, 2 batches each
#pragma unroll 1
        for (int i = 0; i < 8; ++i) {
            int pl = w * 8 + i;
            int p = p0 + pl;
            if (p >= PP) continue;
            float cs = s_scs[pl];
#pragma unroll 1
            for (int bhh = 0; bhh < 2; ++bhh) {
                int b = b0 + bhh;
                float v0 = S[pl * SSTR + bhh * 64 + lane];
                float v1 = S[pl * SSTR + bhh * 64 + 32 + lane];
                size_t obase = ((size_t)b * 1000 + p) * 64 + lane;
                __stcs(&dout[OFF_COSV + obase], v0);
                __stcs(&dout[OFF_COSV + obase + 32], v1);
                __stcs(&dout[OFF_COSD + obase], 1.f - v0);
                __stcs(&dout[OFF_COSD + obase + 32], 1.f - v1);

                float val; int idx;
                if (v1 > v0) { val = v1; idx = lane + 32; } else { val = v0; idx = lane; }
#pragma unroll
                for (int off = 16; off; off >>= 1) {
                    float ov = __shfl_down_sync(0xffffffffu, val, off);
                    int   oi = __shfl_down_sync(0xffffffffu, idx, off);
                    if (ov > val || (ov == val && oi < idx)) { val = ov; idx = oi; }
                }
                val = __shfl_sync(0xffffffffu, val, 0);
                idx = __shfl_sync(0xffffffffu, idx, 0);

                float thr = val - EPS_TIE;
                unsigned mk0 = __ballot_sync(0xffffffffu, v0 >= thr);
                unsigned mk1 = __ballot_sync(0xffffffffu, v1 >= thr);
                if (__popc(mk0) + __popc(mk1) > 1) {
                    const float* pt = g_protoT + (size_t)p * CC;
                    float best = -3e38f; int bidx = 0;
                    unsigned rem0 = mk0, rem1 = mk1;
                    while (rem0 | rem1) {
                        int m;
                        if (rem0) { m = __ffs(rem0) - 1; rem0 &= rem0 - 1; }
                        else      { m = __ffs(rem1) + 31; rem1 &= rem1 - 1; }
                        const float* fn = g_fNraw + ((size_t)(b * 64 + m)) * CC;
                        float s = 0.f;
                        for (int c = lane * 4; c < CC; c += 128) {
                            float4 a = *(const float4*)&fn[c];
                            float4 qq = *(const float4*)&pt[c];
                            s += a.x * qq.x + a.y * qq.y + a.z * qq.z + a.w * qq.w;
                        }
#pragma unroll
                        for (int off = 16; off; off >>= 1)
                            s += __shfl_xor_sync(0xffffffffu, s, off);
                        float ev = s * s_srs[bhh * 64 + m] * cs;
                        if (ev > best) { best = ev; bidx = m; }
                    }
                    val = best;
                    idx = bidx;
                }

                if (lane == 0) {
                    int pair = b * 1000 + p;
                    dout[OFF_SIM + pair] = val;
                    float ww = wgt[p], wee = wgte[p];
                    float sg = 1.f / (1.f + expf(-wee));
                    dout[OFF_CONTRIB + pair] = val * ww * sg;
                    dout[OFF_ARGMAX + pair] = (float)idx;
                }

                if (tile == 0) {
                    // defer the maxfs write into tile-1's mainloop
                    if (lane == 0) {
                        int row = pl * 2 + bhh;
                        s_rowsrc[row] = b * 64 + idx;
                        s_rowscale[row] = g_inv_norm[b * 64 + idx];
                        s_pairdst[row] = b * 1000 + p;
                    }
                } else {
                    // inline maxfs write (batched for MLP)
                    float r1 = g_inv_norm[b * 64 + idx];
                    const float4* src = (const float4*)g_fNraw + ((size_t)(b * 64 + idx)) * 512;
                    float4* dst = (float4*)(dout + OFF_MAXFS) + ((size_t)(b * 1000 + p)) * 512;
#pragma unroll
                    for (int half = 0; half < 2; ++half) {
                        float4 vv[8];
#pragma unroll
                        for (int it = 0; it < 8; ++it)
                            vv[it] = src[(half * 8 + it) * 32 + lane];
#pragma unroll
                        for (int it = 0; it < 8; ++it) {
                            float4 v = vv[it];
                            v.x *= r1; v.y *= r1; v.z *= r1; v.w *= r1;
                            __stcs(&dst[(half * 8 + it) * 32 + lane], v);
                        }
                    }
                }
            }
        }
        __syncthreads();   // S reads + deferred-state writes done before next tile
    }
}

// ---------------------------------------------------------------------------
// 5) out[b][nc] = sum over npr of contrib
// ---------------------------------------------------------------------------
__global__ void outsum_kernel(float* __restrict__ dout) {
    int id = blockIdx.x * 256 + threadIdx.x;
    if (id >= 6400) return;
    const float* c = dout + OFF_CONTRIB + (size_t)id * 10;
    float s = 0.f;
#pragma unroll
    for (int q = 0; q < 10; ++q) s += c[q];
    dout[OFF_OUT + id] = s;
}

// ---------------------------------------------------------------------------
extern "C" void kernel_launch(void* const* d_in, const int* in_sizes, int n_in,
                              void* d_out, int out_size) {
    const float* x     = (const float*)d_in[0];
    const float* proto = (const float*)d_in[1];
    const float* w     = (const float*)d_in[2];
    const float* we    = (const float*)d_in[3];
    float* out = (float*)d_out;

    cudaFuncSetAttribute(mma_kernel, cudaFuncAttributeMaxDynamicSharedMemorySize, MMA_SMEM);

    poolpack_kernel<<<dim3(128, 64), 256>>>(x);
    bpackcol_kernel<<<2048, 256>>>(proto);
    norm_kernel<<<64, 256>>>();
    mma_kernel<<<dim3(16, 16), 256, MMA_SMEM>>>(w, we, out);   // 4th launch -> profiled
    outsum_kernel<<<25, 256>>>(out);
}

// round 14
// speedup vs baseline: 1.2734x; 1.2734x over previous
#include <cuda_runtime.h>
#include <cuda_bf16.h>
#include <math.h>
#include <stdint.h>

// Problem constants
#define BB 64
#define CC 2048
#define MM 64      // 8*8 pooled positions
#define PP 1000    // 100 classes * 10 protos
#define EPS_TIE 3e-5f

// Output segment offsets (floats), tuple order:
// out, contrib, sim_r, cosvalue_u, cosdist_u, maxfs_u, argmaxdist
#define OFF_OUT      0ull
#define OFF_CONTRIB  6400ull
#define OFF_SIM      70400ull
#define OFF_COSV     134400ull
#define OFF_COSD     4230400ull
#define OFF_MAXFS    8326400ull
#define OFF_ARGMAX   139398400ull

// Scratch (device globals: allocation-free rule)
static __device__ float g_fNraw[(size_t)BB * MM * CC];     // pooled, [b][m][c] (unnormalized)
static __device__ float g_protoT[(size_t)1024 * CC];       // raw proto, p-major
// bf16 fragment-packed operands for m16n8k16:
// A: [mt(256)][kq(128)][lane(32)][4 u32], B: [nt(128)][kq(128)][lane(32)][2 u32]
static __device__ uint32_t g_Ah[(size_t)256 * 128 * 32 * 4];
static __device__ uint32_t g_Al[(size_t)256 * 128 * 32 * 4];
static __device__ uint32_t g_Bh[(size_t)128 * 128 * 32 * 2];
static __device__ uint32_t g_Bl[(size_t)128 * 128 * 32 * 2];
static __device__ float g_cpart2[16][1024];                // proto sumsq partials [chunk][p]
static __device__ float g_inv_norm[BB * MM];
static __device__ float g_row_scale[BB * MM];

__device__ __forceinline__ uint32_t smem_u32(const void* p) {
    uint32_t a;
    asm("{ .reg .u64 t; cvta.to.shared.u64 t, %1; cvt.u32.u64 %0, t; }" : "=r"(a) : "l"(p));
    return a;
}
__device__ __forceinline__ float bfh(float v) {
    return __bfloat162float(__float2bfloat16_rn(v));
}
__device__ __forceinline__ uint32_t pack_bf(float lo, float hi) {
    uint32_t r;
    asm("cvt.rn.bf16x2.f32 %0, %1, %2;" : "=r"(r) : "f"(hi), "f"(lo));
    return r;
}
#define CP_ASYNC16(sm, gp) \
    asm volatile("cp.async.cg.shared.global [%0], [%1], 16;" :: "r"(sm), "l"(gp))
#define CP_COMMIT() asm volatile("cp.async.commit_group;" ::: "memory")
#define CP_WAIT2()  asm volatile("cp.async.wait_group 2;" ::: "memory")
#define CP_WAIT0()  asm volatile("cp.async.wait_group 0;" ::: "memory")
#define MMA_BF16(d, a, b) \
    asm volatile("mma.sync.aligned.m16n8k16.row.col.f32.bf16.bf16.f32 " \
        "{%0,%1,%2,%3}, {%4,%5,%6,%7}, {%8,%9}, {%0,%1,%2,%3};" \
        : "+f"((d)[0]), "+f"((d)[1]), "+f"((d)[2]), "+f"((d)[3]) \
        : "r"((a)[0]), "r"((a)[1]), "r"((a)[2]), "r"((a)[3]), \
          "r"((b)[0]), "r"((b)[1]))

// ---------------------------------------------------------------------------
// 1) Fused pool (16x16 -> 8x8) + transposed fNraw write + bf16 A-frag pack.
// ---------------------------------------------------------------------------
__global__ void poolpack_kernel(const float* __restrict__ x) {
    __shared__ float sp[16][72];
    int t = threadIdx.x;
    int kq = blockIdx.x;    // 0..127
    int b = blockIdx.y;     // 0..63
#pragma unroll
    for (int i = 0; i < 2; ++i) {
        int u = t + i * 256;            // 0..511
        int cl = u >> 5;                 // 0..15
        int m2 = (u & 31) * 2;
        int c = kq * 16 + cl;
        int ii = m2 >> 3, j = m2 & 7;    // j even
        const float* xp = x + ((size_t)(b * CC + c)) * 256;
        float4 r0 = *(const float4*)&xp[(2 * ii) * 16 + 2 * j];
        float4 r1 = *(const float4*)&xp[(2 * ii + 1) * 16 + 2 * j];
        sp[cl][m2]     = 0.25f * ((r0.x + r0.y) + (r1.x + r1.y));
        sp[cl][m2 + 1] = 0.25f * ((r0.z + r0.w) + (r1.z + r1.w));
    }
    __syncthreads();
    // transposed write: fNraw[b][m][kq*16 + c]
    {
        int m = t >> 2, c4 = (t & 3) * 4;
        float4 o = make_float4(sp[c4][m], sp[c4 + 1][m], sp[c4 + 2][m], sp[c4 + 3][m]);
        *(float4*)&g_fNraw[((size_t)(b * 64 + m)) * CC + kq * 16 + c4] = o;
    }
    // A fragment pack (hi/lo split)
    int h = t >> 7;        // 0: hi, 1: lo
    int q = t & 127;
    int f = q >> 5, lane = q & 31;
    int g = lane >> 2, tig = lane & 3;
    int m = f * 16 + g;
    float vals[8];
    vals[0] = sp[2 * tig][m];       vals[1] = sp[2 * tig + 1][m];
    vals[2] = sp[2 * tig][m + 8];   vals[3] = sp[2 * tig + 1][m + 8];
    vals[4] = sp[2 * tig + 8][m];     vals[5] = sp[2 * tig + 9][m];
    vals[6] = sp[2 * tig + 8][m + 8]; vals[7] = sp[2 * tig + 9][m + 8];
    uint32_t out[4];
#pragma unroll
    for (int r = 0; r < 4; ++r) {
        float e = vals[2 * r], o = vals[2 * r + 1];
        if (h == 0) out[r] = pack_bf(e, o);
        else        out[r] = pack_bf(e - bfh(e), o - bfh(o));
    }
    size_t idx = (((size_t)(b * 4 + f) * 128 + kq) * 32 + lane) * 4;
    if (h == 0) *(uint4*)&g_Ah[idx] = make_uint4(out[0], out[1], out[2], out[3]);
    else        *(uint4*)&g_Al[idx] = make_uint4(out[0], out[1], out[2], out[3]);
}

// ---------------------------------------------------------------------------
// 2) B fragment pack (bf16 split) + raw protoT + fused column-sumsq partials.
// ---------------------------------------------------------------------------
__global__ void bpackcol_kernel(const float* __restrict__ proto) {
    __shared__ float sq[8][8];
    int t = threadIdx.x;
    int gt = blockIdx.x * 256 + t;             // 0 .. 524287
    int lane = gt & 31;
    int frag = gt >> 5;                         // nt*128 + kq
    int kq = frag & 127, nt = frag >> 7;
    int g = lane >> 2, tig = lane & 3;
    int p = nt * 8 + g;
    int kb = kq * 16;
    float v0 = 0.f, v1 = 0.f, v2 = 0.f, v3 = 0.f;
    if (p < PP) {
        v0 = proto[(size_t)(kb + 2 * tig) * PP + p];
        v1 = proto[(size_t)(kb + 2 * tig + 1) * PP + p];
        v2 = proto[(size_t)(kb + 2 * tig + 8) * PP + p];
        v3 = proto[(size_t)(kb + 2 * tig + 9) * PP + p];
    }
    uint32_t b0h = pack_bf(v0, v1), b1h = pack_bf(v2, v3);
    uint32_t b0l = pack_bf(v0 - bfh(v0), v1 - bfh(v1));
    uint32_t b1l = pack_bf(v2 - bfh(v2), v3 - bfh(v3));
    size_t o = (size_t)frag * 64 + lane * 2;
    *(uint2*)&g_Bh[o] = make_uint2(b0h, b1h);
    *(uint2*)&g_Bl[o] = make_uint2(b0l, b1l);
    if (p < PP) {
        g_protoT[(size_t)p * CC + kb + 2 * tig]     = v0;
        g_protoT[(size_t)p * CC + kb + 2 * tig + 1] = v1;
        g_protoT[(size_t)p * CC + kb + 2 * tig + 8] = v2;
        g_protoT[(size_t)p * CC + kb + 2 * tig + 9] = v3;
    }
    float ss = v0 * v0 + v1 * v1 + v2 * v2 + v3 * v3;
    ss += __shfl_xor_sync(0xffffffffu, ss, 1);
    ss += __shfl_xor_sync(0xffffffffu, ss, 2);
    int wloc = t >> 5;
    if (tig == 0) sq[wloc][g] = ss;
    __syncthreads();
    if (t < 8) {
        float s = 0.f;
#pragma unroll
        for (int w2 = 0; w2 < 8; ++w2) s += sq[w2][t];
        int ntb = (blockIdx.x * 8) >> 7;
        int chunk = blockIdx.x & 15;
        g_cpart2[chunk][ntb * 8 + t] = s;
    }
}

// ---------------------------------------------------------------------------
// 3) Row norms: coalesced over fNraw rows
// ---------------------------------------------------------------------------
__global__ void norm_kernel() {
    int b = blockIdx.x;
    int w = threadIdx.x >> 5, lane = threadIdx.x & 31;
#pragma unroll
    for (int i = 0; i < 8; ++i) {
        int m = w * 8 + i;
        const float4* row = (const float4*)(g_fNraw + ((size_t)(b * 64 + m)) * CC);
        float s = 0.f;
        for (int c = lane; c < 512; c += 32) {
            float4 v = row[c];
            s += v.x * v.x + v.y * v.y + v.z * v.z + v.w * v.w;
        }
#pragma unroll
        for (int off = 16; off; off >>= 1)
            s += __shfl_xor_sync(0xffffffffu, s, off);
        if (lane == 0) {
            float s1 = sqrtf(s);
            float r1 = 1.f / fmaxf(s1, 1e-12f);
            float na = s1 * r1 + 1e-3f;
            g_inv_norm[b * 64 + m] = r1;
            g_row_scale[b * 64 + m] = r1 / na;
        }
    }
}

// ---------------------------------------------------------------------------
// 4) bf16 3-split mma.sync GEMM + full fused epilogue.
//    Tile 128 rows (2 b) x 64 p, grid 16x32 = 512 CTAs, 2 CTAs/SM.
//    4-stage k32 ring, ONE __syncthreads per kt, loads issued before compute.
//    Stage = 24KB: Ah[0,8K) Al[8K,16K) Bh[16K,20K) Bl[20K,24K).
// ---------------------------------------------------------------------------
#define STAGE 24576
#define SSTR 129
__global__ __launch_bounds__(256, 2) void mma_kernel(const float* __restrict__ wgt,
                                                     const float* __restrict__ wgte,
                                                     float* __restrict__ dout) {
    extern __shared__ char smem[];
    uint32_t sb = smem_u32(smem);
    int t = threadIdx.x;
    int lane = t & 31, w = t >> 5;
    int wm = w & 1, wn = w >> 1;
    int mt0 = blockIdx.y * 8;
    int nt0 = blockIdx.x * 8;

    float acc[4][2][4];
#pragma unroll
    for (int i = 0; i < 4; ++i)
#pragma unroll
        for (int j = 0; j < 2; ++j)
#pragma unroll
            for (int q = 0; q < 4; ++q) acc[i][j][q] = 0.f;

    auto load_stage = [&](int sbuf, int kt) {
        uint32_t st = sb + sbuf * STAGE;
        int k0q = kt * 2;
#pragma unroll
        for (int i = 0; i < 2; ++i) {
            int q = t + i * 256;               // 0..511
            int frag = q >> 5, off = q & 31;   // frag = kq2*8 + mtl
            int kq2 = frag >> 3, mtl = frag & 7;
            size_t gidx = (((size_t)(mt0 + mtl) * 128) + k0q + kq2) * 128 + off * 4;
            CP_ASYNC16(st + frag * 512 + off * 16, g_Ah + gidx);
            CP_ASYNC16(st + 8192 + frag * 512 + off * 16, g_Al + gidx);
        }
        {
            int frag = t >> 4, off = t & 15;   // frag = kq2*8 + ntl
            int kq2 = frag >> 3, ntl = frag & 7;
            size_t gidx = (((size_t)(nt0 + ntl) * 128) + k0q + kq2) * 64 + off * 4;
            CP_ASYNC16(st + 16384 + frag * 256 + off * 16, g_Bh + gidx);
            CP_ASYNC16(st + 20480 + frag * 256 + off * 16, g_Bl + gidx);
        }
    };

    load_stage(0, 0); CP_COMMIT();
    load_stage(1, 1); CP_COMMIT();
    load_stage(2, 2); CP_COMMIT();

    for (int kt = 0; kt < 64; ++kt) {
        CP_WAIT2();             // stage kt resident
        __syncthreads();        // all warps done with stage kt-1 (refill target)
        if (kt < 61) load_stage((kt + 3) & 3, kt + 3);   // refill (kt-1)'s slot
        uint32_t st = sb + (kt & 3) * STAGE;
#pragma unroll
        for (int kq2 = 0; kq2 < 2; ++kq2) {
            uint32_t bh[2][2], bl[2][2];
#pragma unroll
            for (int nt = 0; nt < 2; ++nt) {
                uint32_t bo = st + 16384 + (uint32_t)((kq2 * 8 + wn * 2 + nt) * 32 + lane) * 8;
                asm("ld.shared.v2.b32 {%0,%1}, [%2];"
                    : "=r"(bh[nt][0]), "=r"(bh[nt][1]) : "r"(bo));
                asm("ld.shared.v2.b32 {%0,%1}, [%2];"
                    : "=r"(bl[nt][0]), "=r"(bl[nt][1]) : "r"(bo + 4096));
            }
#pragma unroll
            for (int mt = 0; mt < 4; ++mt) {
                uint32_t ah[4], al[4];
                uint32_t ao = st + (uint32_t)((kq2 * 8 + wm * 4 + mt) * 32 + lane) * 16;
                asm("ld.shared.v4.b32 {%0,%1,%2,%3}, [%4];"
                    : "=r"(ah[0]), "=r"(ah[1]), "=r"(ah[2]), "=r"(ah[3]) : "r"(ao));
                asm("ld.shared.v4.b32 {%0,%1,%2,%3}, [%4];"
                    : "=r"(al[0]), "=r"(al[1]), "=r"(al[2]), "=r"(al[3]) : "r"(ao + 8192));
#pragma unroll
                for (int nt = 0; nt < 2; ++nt) {
                    MMA_BF16(acc[mt][nt], ah, bh[nt]);
                    MMA_BF16(acc[mt][nt], ah, bl[nt]);
                    MMA_BF16(acc[mt][nt], al, bh[nt]);
                }
            }
        }
        CP_COMMIT();
    }
    CP_WAIT0();
    __syncthreads();

    // ---- epilogue ----
    float* S   = (float*)smem;                  // [64][SSTR]
    float* scs = S + 64 * SSTR;                 // col_scale [64]
    float* srs = scs + 64;                      // row_scale [128]
    int p0 = blockIdx.x * 64;
    int b0 = blockIdx.y * 2;
    if (t < 64) {
        int p = p0 + t;
        float s = 0.f;
#pragma unroll
        for (int ch = 0; ch < 16; ++ch) s += g_cpart2[ch][p];
        float s1 = sqrtf(s);
        float r1 = 1.f / fmaxf(s1, 1e-12f);
        scs[t] = r1 / (s1 * r1 + 1e-3f);
    } else if (t >= 128) {
        srs[t - 128] = g_row_scale[b0 * 64 + (t - 128)];
    }
    __syncthreads();

    int g = lane >> 2, tig = lane & 3;
#pragma unroll
    for (int mt = 0; mt < 4; ++mt) {
        int ml0 = (wm * 4 + mt) * 16 + g;
#pragma unroll
        for (int nt = 0; nt < 2; ++nt) {
            int pl = (wn * 2 + nt) * 8 + tig * 2;
            S[pl * SSTR + ml0]           = acc[mt][nt][0] * srs[ml0] * scs[pl];
            S[(pl + 1) * SSTR + ml0]     = acc[mt][nt][1] * srs[ml0] * scs[pl + 1];
            S[pl * SSTR + ml0 + 8]       = acc[mt][nt][2] * srs[ml0 + 8] * scs[pl];
            S[(pl + 1) * SSTR + ml0 + 8] = acc[mt][nt][3] * srs[ml0 + 8] * scs[pl + 1];
        }
    }
    __syncthreads();

    // per-warp: 8 p-columns, 2 batches each
#pragma unroll 1
    for (int i = 0; i < 8; ++i) {
        int pl = w * 8 + i;
        int p = p0 + pl;
        if (p >= PP) continue;
        float cs = scs[pl];
#pragma unroll 1
        for (int bhh = 0; bhh < 2; ++bhh) {
            int b = b0 + bhh;
            float v0 = S[pl * SSTR + bhh * 64 + lane];
            float v1 = S[pl * SSTR + bhh * 64 + 32 + lane];
            size_t obase = ((size_t)b * 1000 + p) * 64 + lane;
            __stcs(&dout[OFF_COSV + obase], v0);
            __stcs(&dout[OFF_COSV + obase + 32], v1);
            __stcs(&dout[OFF_COSD + obase], 1.f - v0);
            __stcs(&dout[OFF_COSD + obase + 32], 1.f - v1);

            float val; int idx;
            if (v1 > v0) { val = v1; idx = lane + 32; } else { val = v0; idx = lane; }
#pragma unroll
            for (int off = 16; off; off >>= 1) {
                float ov = __shfl_down_sync(0xffffffffu, val, off);
                int   oi = __shfl_down_sync(0xffffffffu, idx, off);
                if (ov > val || (ov == val && oi < idx)) { val = ov; idx = oi; }
            }
            val = __shfl_sync(0xffffffffu, val, 0);
            idx = __shfl_sync(0xffffffffu, idx, 0);

            float thr = val - EPS_TIE;
            unsigned mk0 = __ballot_sync(0xffffffffu, v0 >= thr);
            unsigned mk1 = __ballot_sync(0xffffffffu, v1 >= thr);
            if (__popc(mk0) + __popc(mk1) > 1) {
                const float* pt = g_protoT + (size_t)p * CC;
                float best = -3e38f; int bidx = 0;
                unsigned rem0 = mk0, rem1 = mk1;
                while (rem0 | rem1) {
                    int m;
                    if (rem0) { m = __ffs(rem0) - 1; rem0 &= rem0 - 1; }
                    else      { m = __ffs(rem1) + 31; rem1 &= rem1 - 1; }
                    const float* fn = g_fNraw + ((size_t)(b * 64 + m)) * CC;
                    float s = 0.f;
                    for (int c = lane * 4; c < CC; c += 128) {
                        float4 a = *(const float4*)&fn[c];
                        float4 qq = *(const float4*)&pt[c];
                        s += a.x * qq.x + a.y * qq.y + a.z * qq.z + a.w * qq.w;
                    }
#pragma unroll
                    for (int off = 16; off; off >>= 1)
                        s += __shfl_xor_sync(0xffffffffu, s, off);
                    float ev = s * srs[bhh * 64 + m] * cs;
                    if (ev > best) { best = ev; bidx = m; }
                }
                val = best;
                idx = bidx;
            }

            if (lane == 0) {
                int pair = b * 1000 + p;
                dout[OFF_SIM + pair] = val;
                float ww = wgt[p], wee = wgte[p];
                float sg = 1.f / (1.f + expf(-wee));
                dout[OFF_CONTRIB + pair] = val * ww * sg;
                dout[OFF_ARGMAX + pair] = (float)idx;
            }

            // maxfs gather: 8KB row, batched load-8 / store-8 for MLP
            float r1 = g_inv_norm[b * 64 + idx];
            const float4* src = (const float4*)g_fNraw + ((size_t)(b * 64 + idx)) * 512;
            float4* dst = (float4*)(dout + OFF_MAXFS) + ((size_t)(b * 1000 + p)) * 512;
#pragma unroll
            for (int half = 0; half < 2; ++half) {
                float4 vv[8];
#pragma unroll
                for (int it = 0; it < 8; ++it)
                    vv[it] = src[(half * 8 + it) * 32 + lane];
#pragma unroll
                for (int it = 0; it < 8; ++it) {
                    float4 v = vv[it];
                    v.x *= r1; v.y *= r1; v.z *= r1; v.w *= r1;
                    __stcs(&dst[(half * 8 + it) * 32 + lane], v);
                }
            }
        }
    }
}

// ---------------------------------------------------------------------------
// 5) out[b][nc] = sum over npr of contrib
// ---------------------------------------------------------------------------
__global__ void outsum_kernel(float* __restrict__ dout) {
    int id = blockIdx.x * 256 + threadIdx.x;
    if (id >= 6400) return;
    const float* c = dout + OFF_CONTRIB + (size_t)id * 10;
    float s = 0.f;
#pragma unroll
    for (int q = 0; q < 10; ++q) s += c[q];
    dout[OFF_OUT + id] = s;
}

// ---------------------------------------------------------------------------
extern "C" void kernel_launch(void* const* d_in, const int* in_sizes, int n_in,
                              void* d_out, int out_size) {
    const float* x     = (const float*)d_in[0];
    const float* proto = (const float*)d_in[1];
    const float* w     = (const float*)d_in[2];
    const float* we    = (const float*)d_in[3];
    float* out = (float*)d_out;

    cudaFuncSetAttribute(mma_kernel, cudaFuncAttributeMaxDynamicSharedMemorySize, 4 * STAGE);

    poolpack_kernel<<<dim3(128, 64), 256>>>(x);
    bpackcol_kernel<<<2048, 256>>>(proto);
    norm_kernel<<<64, 256>>>();
    mma_kernel<<<dim3(16, 32), 256, 4 * STAGE>>>(w, we, out);   // 4th launch -> profiled
    outsum_kernel<<<25, 256>>>(out);
}

// round 15
// speedup vs baseline: 1.3352x; 1.0485x over previous
#include <cuda_runtime.h>
#include <cuda_bf16.h>
#include <math.h>
#include <stdint.h>

// Problem constants
#define BB 64
#define CC 2048
#define MM 64      // 8*8 pooled positions
#define PP 1000    // 100 classes * 10 protos
#define EPS_TIE 3e-5f

// Output segment offsets (floats), tuple order:
// out, contrib, sim_r, cosvalue_u, cosdist_u, maxfs_u, argmaxdist
#define OFF_OUT      0ull
#define OFF_CONTRIB  6400ull
#define OFF_SIM      70400ull
#define OFF_COSV     134400ull
#define OFF_COSD     4230400ull
#define OFF_MAXFS    8326400ull
#define OFF_ARGMAX   139398400ull

// Scratch (device globals: allocation-free rule)
static __device__ float g_fNraw[(size_t)BB * MM * CC];     // pooled, [b][m][c] (unnormalized)
static __device__ float g_protoT[(size_t)1024 * CC];       // raw proto, p-major
// bf16 fragment-packed operands for m16n8k16:
// A: [mt(256)][kq(128)][lane(32)][4 u32], B: [nt(128)][kq(128)][lane(32)][2 u32]
static __device__ uint32_t g_Ah[(size_t)256 * 128 * 32 * 4];
static __device__ uint32_t g_Al[(size_t)256 * 128 * 32 * 4];
static __device__ uint32_t g_Bh[(size_t)128 * 128 * 32 * 2];
static __device__ uint32_t g_Bl[(size_t)128 * 128 * 32 * 2];
static __device__ float g_cpart2[16][1024];                // proto sumsq partials [chunk][p]
static __device__ float g_npart[128][BB * MM];             // row sumsq partials [kq][row]
static __device__ float g_inv_norm[BB * MM];
static __device__ float g_row_scale[BB * MM];

__device__ __forceinline__ uint32_t smem_u32(const void* p) {
    uint32_t a;
    asm("{ .reg .u64 t; cvta.to.shared.u64 t, %1; cvt.u32.u64 %0, t; }" : "=r"(a) : "l"(p));
    return a;
}
__device__ __forceinline__ float bfh(float v) {
    return __bfloat162float(__float2bfloat16_rn(v));
}
__device__ __forceinline__ uint32_t pack_bf(float lo, float hi) {
    uint32_t r;
    asm("cvt.rn.bf16x2.f32 %0, %1, %2;" : "=r"(r) : "f"(hi), "f"(lo));
    return r;
}
#define CP_ASYNC16(sm, gp) \
    asm volatile("cp.async.cg.shared.global [%0], [%1], 16;" :: "r"(sm), "l"(gp))
#define CP_COMMIT() asm volatile("cp.async.commit_group;" ::: "memory")
#define CP_WAIT2()  asm volatile("cp.async.wait_group 2;" ::: "memory")
#define CP_WAIT0()  asm volatile("cp.async.wait_group 0;" ::: "memory")
#define MMA_BF16(d, a, b) \
    asm volatile("mma.sync.aligned.m16n8k16.row.col.f32.bf16.bf16.f32 " \
        "{%0,%1,%2,%3}, {%4,%5,%6,%7}, {%8,%9}, {%0,%1,%2,%3};" \
        : "+f"((d)[0]), "+f"((d)[1]), "+f"((d)[2]), "+f"((d)[3]) \
        : "r"((a)[0]), "r"((a)[1]), "r"((a)[2]), "r"((a)[3]), \
          "r"((b)[0]), "r"((b)[1]))

// ---------------------------------------------------------------------------
// 1) Fused pack kernel.
//    Blocks [0, 8192): pool (16x16 -> 8x8) + transposed fNraw write +
//                      bf16 A-frag pack + row-sumsq partials.
//    Blocks [8192, 10240): B fragment pack + protoT + column-sumsq partials.
// ---------------------------------------------------------------------------
__global__ void pack_kernel(const float* __restrict__ x,
                            const float* __restrict__ proto) {
    __shared__ float sp[16][72];
    __shared__ float sq[8][8];
    int t = threadIdx.x;
    if (blockIdx.x < 8192) {
        // ---- pool + A pack ----
        int blk = blockIdx.x;
        int kq = blk & 127;
        int b = blk >> 7;
#pragma unroll
        for (int i = 0; i < 2; ++i) {
            int u = t + i * 256;            // 0..511
            int cl = u >> 5;                 // 0..15
            int m2 = (u & 31) * 2;
            int c = kq * 16 + cl;
            int ii = m2 >> 3, j = m2 & 7;    // j even
            const float* xp = x + ((size_t)(b * CC + c)) * 256;
            float4 r0 = *(const float4*)&xp[(2 * ii) * 16 + 2 * j];
            float4 r1 = *(const float4*)&xp[(2 * ii + 1) * 16 + 2 * j];
            sp[cl][m2]     = 0.25f * ((r0.x + r0.y) + (r1.x + r1.y));
            sp[cl][m2 + 1] = 0.25f * ((r0.z + r0.w) + (r1.z + r1.w));
        }
        __syncthreads();
        // transposed write: fNraw[b][m][kq*16 + c]
        {
            int m = t >> 2, c4 = (t & 3) * 4;
            float4 o = make_float4(sp[c4][m], sp[c4 + 1][m], sp[c4 + 2][m], sp[c4 + 3][m]);
            *(float4*)&g_fNraw[((size_t)(b * 64 + m)) * CC + kq * 16 + c4] = o;
        }
        // row sumsq partial for this kq chunk (threads 0..63, conflict-free col reads)
        if (t < 64) {
            float s = 0.f;
#pragma unroll
            for (int cl = 0; cl < 16; ++cl) {
                float v = sp[cl][t];
                s += v * v;
            }
            g_npart[kq][b * 64 + t] = s;
        }
        // A fragment pack (hi/lo split)
        int h = t >> 7;        // 0: hi, 1: lo
        int q = t & 127;
        int f = q >> 5, lane = q & 31;
        int g = lane >> 2, tig = lane & 3;
        int m = f * 16 + g;
        float vals[8];
        vals[0] = sp[2 * tig][m];       vals[1] = sp[2 * tig + 1][m];
        vals[2] = sp[2 * tig][m + 8];   vals[3] = sp[2 * tig + 1][m + 8];
        vals[4] = sp[2 * tig + 8][m];     vals[5] = sp[2 * tig + 9][m];
        vals[6] = sp[2 * tig + 8][m + 8]; vals[7] = sp[2 * tig + 9][m + 8];
        uint32_t out[4];
#pragma unroll
        for (int r = 0; r < 4; ++r) {
            float e = vals[2 * r], o = vals[2 * r + 1];
            if (h == 0) out[r] = pack_bf(e, o);
            else        out[r] = pack_bf(e - bfh(e), o - bfh(o));
        }
        size_t idx = (((size_t)(b * 4 + f) * 128 + kq) * 32 + lane) * 4;
        if (h == 0) *(uint4*)&g_Ah[idx] = make_uint4(out[0], out[1], out[2], out[3]);
        else        *(uint4*)&g_Al[idx] = make_uint4(out[0], out[1], out[2], out[3]);
    } else {
        // ---- B pack + col sumsq ----
        int bx = blockIdx.x - 8192;                // 0..2047
        int gt = bx * 256 + t;                     // 0 .. 524287
        int lane = gt & 31;
        int frag = gt >> 5;                         // nt*128 + kq
        int kq = frag & 127, nt = frag >> 7;
        int g = lane >> 2, tig = lane & 3;
        int p = nt * 8 + g;
        int kb = kq * 16;
        float v0 = 0.f, v1 = 0.f, v2 = 0.f, v3 = 0.f;
        if (p < PP) {
            v0 = proto[(size_t)(kb + 2 * tig) * PP + p];
            v1 = proto[(size_t)(kb + 2 * tig + 1) * PP + p];
            v2 = proto[(size_t)(kb + 2 * tig + 8) * PP + p];
            v3 = proto[(size_t)(kb + 2 * tig + 9) * PP + p];
        }
        uint32_t b0h = pack_bf(v0, v1), b1h = pack_bf(v2, v3);
        uint32_t b0l = pack_bf(v0 - bfh(v0), v1 - bfh(v1));
        uint32_t b1l = pack_bf(v2 - bfh(v2), v3 - bfh(v3));
        size_t o = (size_t)frag * 64 + lane * 2;
        *(uint2*)&g_Bh[o] = make_uint2(b0h, b1h);
        *(uint2*)&g_Bl[o] = make_uint2(b0l, b1l);
        if (p < PP) {
            g_protoT[(size_t)p * CC + kb + 2 * tig]     = v0;
            g_protoT[(size_t)p * CC + kb + 2 * tig + 1] = v1;
            g_protoT[(size_t)p * CC + kb + 2 * tig + 8] = v2;
            g_protoT[(size_t)p * CC + kb + 2 * tig + 9] = v3;
        }
        float ss = v0 * v0 + v1 * v1 + v2 * v2 + v3 * v3;
        ss += __shfl_xor_sync(0xffffffffu, ss, 1);
        ss += __shfl_xor_sync(0xffffffffu, ss, 2);
        int wloc = t >> 5;
        if (tig == 0) sq[wloc][g] = ss;
        __syncthreads();
        if (t < 8) {
            float s = 0.f;
#pragma unroll
            for (int w2 = 0; w2 < 8; ++w2) s += sq[w2][t];
            int ntb = (bx * 8) >> 7;
            int chunk = bx & 15;
            g_cpart2[chunk][ntb * 8 + t] = s;
        }
    }
}

// ---------------------------------------------------------------------------
// 2) Row-norm finalize: sum 128 kq-partials per row (coalesced across threads)
// ---------------------------------------------------------------------------
__global__ void normfin_kernel() {
    int r = blockIdx.x * 256 + threadIdx.x;    // 0..4095
    float s = 0.f;
#pragma unroll 8
    for (int kq = 0; kq < 128; ++kq) s += g_npart[kq][r];
    float s1 = sqrtf(s);
    float r1 = 1.f / fmaxf(s1, 1e-12f);
    float na = s1 * r1 + 1e-3f;
    g_inv_norm[r] = r1;
    g_row_scale[r] = r1 / na;
}

// ---------------------------------------------------------------------------
// 3) bf16 3-split mma.sync GEMM + full fused epilogue (proven round-12 form).
//    Tile 128 rows (2 b) x 64 p, grid 16x32 = 512 CTAs, 2 CTAs/SM.
//    4-stage k32 ring, ONE __syncthreads per kt, loads issued before compute.
//    Stage = 24KB: Ah[0,8K) Al[8K,16K) Bh[16K,20K) Bl[20K,24K).
// ---------------------------------------------------------------------------
#define STAGE 24576
#define SSTR 129
__global__ __launch_bounds__(256, 2) void mma_kernel(const float* __restrict__ wgt,
                                                     const float* __restrict__ wgte,
                                                     float* __restrict__ dout) {
    extern __shared__ char smem[];
    uint32_t sb = smem_u32(smem);
    int t = threadIdx.x;
    int lane = t & 31, w = t >> 5;
    int wm = w & 1, wn = w >> 1;
    int mt0 = blockIdx.y * 8;
    int nt0 = blockIdx.x * 8;

    float acc[4][2][4];
#pragma unroll
    for (int i = 0; i < 4; ++i)
#pragma unroll
        for (int j = 0; j < 2; ++j)
#pragma unroll
            for (int q = 0; q < 4; ++q) acc[i][j][q] = 0.f;

    auto load_stage = [&](int sbuf, int kt) {
        uint32_t st = sb + sbuf * STAGE;
        int k0q = kt * 2;
#pragma unroll
        for (int i = 0; i < 2; ++i) {
            int q = t + i * 256;               // 0..511
            int frag = q >> 5, off = q & 31;   // frag = kq2*8 + mtl
            int kq2 = frag >> 3, mtl = frag & 7;
            size_t gidx = (((size_t)(mt0 + mtl) * 128) + k0q + kq2) * 128 + off * 4;
            CP_ASYNC16(st + frag * 512 + off * 16, g_Ah + gidx);
            CP_ASYNC16(st + 8192 + frag * 512 + off * 16, g_Al + gidx);
        }
        {
            int frag = t >> 4, off = t & 15;   // frag = kq2*8 + ntl
            int kq2 = frag >> 3, ntl = frag & 7;
            size_t gidx = (((size_t)(nt0 + ntl) * 128) + k0q + kq2) * 64 + off * 4;
            CP_ASYNC16(st + 16384 + frag * 256 + off * 16, g_Bh + gidx);
            CP_ASYNC16(st + 20480 + frag * 256 + off * 16, g_Bl + gidx);
        }
    };

    load_stage(0, 0); CP_COMMIT();
    load_stage(1, 1); CP_COMMIT();
    load_stage(2, 2); CP_COMMIT();

    for (int kt = 0; kt < 64; ++kt) {
        CP_WAIT2();             // stage kt resident
        __syncthreads();        // all warps done with stage kt-1 (refill target)
        if (kt < 61) load_stage((kt + 3) & 3, kt + 3);   // refill (kt-1)'s slot
        uint32_t st = sb + (kt & 3) * STAGE;
#pragma unroll
        for (int kq2 = 0; kq2 < 2; ++kq2) {
            uint32_t bh[2][2], bl[2][2];
#pragma unroll
            for (int nt = 0; nt < 2; ++nt) {
                uint32_t bo = st + 16384 + (uint32_t)((kq2 * 8 + wn * 2 + nt) * 32 + lane) * 8;
                asm("ld.shared.v2.b32 {%0,%1}, [%2];"
                    : "=r"(bh[nt][0]), "=r"(bh[nt][1]) : "r"(bo));
                asm("ld.shared.v2.b32 {%0,%1}, [%2];"
                    : "=r"(bl[nt][0]), "=r"(bl[nt][1]) : "r"(bo + 4096));
            }
#pragma unroll
            for (int mt = 0; mt < 4; ++mt) {
                uint32_t ah[4], al[4];
                uint32_t ao = st + (uint32_t)((kq2 * 8 + wm * 4 + mt) * 32 + lane) * 16;
                asm("ld.shared.v4.b32 {%0,%1,%2,%3}, [%4];"
                    : "=r"(ah[0]), "=r"(ah[1]), "=r"(ah[2]), "=r"(ah[3]) : "r"(ao));
                asm("ld.shared.v4.b32 {%0,%1,%2,%3}, [%4];"
                    : "=r"(al[0]), "=r"(al[1]), "=r"(al[2]), "=r"(al[3]) : "r"(ao + 8192));
#pragma unroll
                for (int nt = 0; nt < 2; ++nt) {
                    MMA_BF16(acc[mt][nt], ah, bh[nt]);
                    MMA_BF16(acc[mt][nt], ah, bl[nt]);
                    MMA_BF16(acc[mt][nt], al, bh[nt]);
                }
            }
        }
        CP_COMMIT();
    }
    CP_WAIT0();
    __syncthreads();

    // ---- epilogue ----
    float* S   = (float*)smem;                  // [64][SSTR]
    float* scs = S + 64 * SSTR;                 // col_scale [64]
    float* srs = scs + 64;                      // row_scale [128]
    int p0 = blockIdx.x * 64;
    int b0 = blockIdx.y * 2;
    if (t < 64) {
        int p = p0 + t;
        float s = 0.f;
#pragma unroll
        for (int ch = 0; ch < 16; ++ch) s += g_cpart2[ch][p];
        float s1 = sqrtf(s);
        float r1 = 1.f / fmaxf(s1, 1e-12f);
        scs[t] = r1 / (s1 * r1 + 1e-3f);
    } else if (t >= 128) {
        srs[t - 128] = g_row_scale[b0 * 64 + (t - 128)];
    }
    __syncthreads();

    int g = lane >> 2, tig = lane & 3;
#pragma unroll
    for (int mt = 0; mt < 4; ++mt) {
        int ml0 = (wm * 4 + mt) * 16 + g;
#pragma unroll
        for (int nt = 0; nt < 2; ++nt) {
            int pl = (wn * 2 + nt) * 8 + tig * 2;
            S[pl * SSTR + ml0]           = acc[mt][nt][0] * srs[ml0] * scs[pl];
            S[(pl + 1) * SSTR + ml0]     = acc[mt][nt][1] * srs[ml0] * scs[pl + 1];
            S[pl * SSTR + ml0 + 8]       = acc[mt][nt][2] * srs[ml0 + 8] * scs[pl];
            S[(pl + 1) * SSTR + ml0 + 8] = acc[mt][nt][3] * srs[ml0 + 8] * scs[pl + 1];
        }
    }
    __syncthreads();

    // per-warp: 8 p-columns, 2 batches each
#pragma unroll 1
    for (int i = 0; i < 8; ++i) {
        int pl = w * 8 + i;
        int p = p0 + pl;
        if (p >= PP) continue;
        float cs = scs[pl];
#pragma unroll 1
        for (int bhh = 0; bhh < 2; ++bhh) {
            int b = b0 + bhh;
            float v0 = S[pl * SSTR + bhh * 64 + lane];
            float v1 = S[pl * SSTR + bhh * 64 + 32 + lane];
            size_t obase = ((size_t)b * 1000 + p) * 64 + lane;
            __stcs(&dout[OFF_COSV + obase], v0);
            __stcs(&dout[OFF_COSV + obase + 32], v1);
            __stcs(&dout[OFF_COSD + obase], 1.f - v0);
            __stcs(&dout[OFF_COSD + obase + 32], 1.f - v1);

            float val; int idx;
            if (v1 > v0) { val = v1; idx = lane + 32; } else { val = v0; idx = lane; }
#pragma unroll
            for (int off = 16; off; off >>= 1) {
                float ov = __shfl_down_sync(0xffffffffu, val, off);
                int   oi = __shfl_down_sync(0xffffffffu, idx, off);
                if (ov > val || (ov == val && oi < idx)) { val = ov; idx = oi; }
            }
            val = __shfl_sync(0xffffffffu, val, 0);
            idx = __shfl_sync(0xffffffffu, idx, 0);

            float thr = val - EPS_TIE;
            unsigned mk0 = __ballot_sync(0xffffffffu, v0 >= thr);
            unsigned mk1 = __ballot_sync(0xffffffffu, v1 >= thr);
            if (__popc(mk0) + __popc(mk1) > 1) {
                const float* pt = g_protoT + (size_t)p * CC;
                float best = -3e38f; int bidx = 0;
                unsigned rem0 = mk0, rem1 = mk1;
                while (rem0 | rem1) {
                    int m;
                    if (rem0) { m = __ffs(rem0) - 1; rem0 &= rem0 - 1; }
                    else      { m = __ffs(rem1) + 31; rem1 &= rem1 - 1; }
                    const float* fn = g_fNraw + ((size_t)(b * 64 + m)) * CC;
                    float s = 0.f;
                    for (int c = lane * 4; c < CC; c += 128) {
                        float4 a = *(const float4*)&fn[c];
                        float4 qq = *(const float4*)&pt[c];
                        s += a.x * qq.x + a.y * qq.y + a.z * qq.z + a.w * qq.w;
                    }
#pragma unroll
                    for (int off = 16; off; off >>= 1)
                        s += __shfl_xor_sync(0xffffffffu, s, off);
                    float ev = s * srs[bhh * 64 + m] * cs;
                    if (ev > best) { best = ev; bidx = m; }
                }
                val = best;
                idx = bidx;
            }

            if (lane == 0) {
                int pair = b * 1000 + p;
                dout[OFF_SIM + pair] = val;
                float ww = wgt[p], wee = wgte[p];
                float sg = 1.f / (1.f + expf(-wee));
                dout[OFF_CONTRIB + pair] = val * ww * sg;
                dout[OFF_ARGMAX + pair] = (float)idx;
            }

            // maxfs gather: 8KB row, batched load-8 / store-8 for MLP
            float r1 = g_inv_norm[b * 64 + idx];
            const float4* src = (const float4*)g_fNraw + ((size_t)(b * 64 + idx)) * 512;
            float4* dst = (float4*)(dout + OFF_MAXFS) + ((size_t)(b * 1000 + p)) * 512;
#pragma unroll
            for (int half = 0; half < 2; ++half) {
                float4 vv[8];
#pragma unroll
                for (int it = 0; it < 8; ++it)
                    vv[it] = src[(half * 8 + it) * 32 + lane];
#pragma unroll
                for (int it = 0; it < 8; ++it) {
                    float4 v = vv[it];
                    v.x *= r1; v.y *= r1; v.z *= r1; v.w *= r1;
                    __stcs(&dst[(half * 8 + it) * 32 + lane], v);
                }
            }
        }
    }
}

// ---------------------------------------------------------------------------
// 4) out[b][nc] = sum over npr of contrib
// ---------------------------------------------------------------------------
__global__ void outsum_kernel(float* __restrict__ dout) {
    int id = blockIdx.x * 256 + threadIdx.x;
    if (id >= 6400) return;
    const float* c = dout + OFF_CONTRIB + (size_t)id * 10;
    float s = 0.f;
#pragma unroll
    for (int q = 0; q < 10; ++q) s += c[q];
    dout[OFF_OUT + id] = s;
}

// ---------------------------------------------------------------------------
extern "C" void kernel_launch(void* const* d_in, const int* in_sizes, int n_in,
                              void* d_out, int out_size) {
    const float* x     = (const float*)d_in[0];
    const float* proto = (const float*)d_in[1];
    const float* w     = (const float*)d_in[2];
    const float* we    = (const float*)d_in[3];
    float* out = (float*)d_out;

    cudaFuncSetAttribute(mma_kernel, cudaFuncAttributeMaxDynamicSharedMemorySize, 4 * STAGE);

    pack_kernel<<<10240, 256>>>(x, proto);
    normfin_kernel<<<16, 256>>>();
    mma_kernel<<<dim3(16, 32), 256, 4 * STAGE>>>(w, we, out);
    outsum_kernel<<<25, 256>>>(out);
}

// round 16
// speedup vs baseline: 1.3467x; 1.0086x over previous
#include <cuda_runtime.h>
#include <cuda_bf16.h>
#include <math.h>
#include <stdint.h>

// Problem constants
#define BB 64
#define CC 2048
#define MM 64      // 8*8 pooled positions
#define PP 1000    // 100 classes * 10 protos
#define EPS_TIE 3e-5f

// Output segment offsets (floats), tuple order:
// out, contrib, sim_r, cosvalue_u, cosdist_u, maxfs_u, argmaxdist
#define OFF_OUT      0ull
#define OFF_CONTRIB  6400ull
#define OFF_SIM      70400ull
#define OFF_COSV     134400ull
#define OFF_COSD     4230400ull
#define OFF_MAXFS    8326400ull
#define OFF_ARGMAX   139398400ull

// Scratch (device globals: allocation-free rule)
static __device__ float g_fNraw[(size_t)BB * MM * CC];     // pooled, [b][m][c] (unnormalized)
static __device__ float g_protoT[(size_t)1024 * CC];       // raw proto, p-major
// bf16 fragment-packed operands for m16n8k16:
// A: [mt(256)][kq(128)][lane(32)][4 u32], B: [nt(128)][kq(128)][lane(32)][2 u32]
static __device__ uint32_t g_Ah[(size_t)256 * 128 * 32 * 4];
static __device__ uint32_t g_Al[(size_t)256 * 128 * 32 * 4];
static __device__ uint32_t g_Bh[(size_t)128 * 128 * 32 * 2];
static __device__ uint32_t g_Bl[(size_t)128 * 128 * 32 * 2];
static __device__ float g_cpart2[16][1024];                // proto sumsq partials [chunk][p]
static __device__ float g_npart[128][BB * MM];             // row sumsq partials [kq][row]
static __device__ float g_inv_norm[BB * MM];
static __device__ float g_row_scale[BB * MM];

__device__ __forceinline__ uint32_t smem_u32(const void* p) {
    uint32_t a;
    asm("{ .reg .u64 t; cvta.to.shared.u64 t, %1; cvt.u32.u64 %0, t; }" : "=r"(a) : "l"(p));
    return a;
}
__device__ __forceinline__ float bfh(float v) {
    return __bfloat162float(__float2bfloat16_rn(v));
}
__device__ __forceinline__ uint32_t pack_bf(float lo, float hi) {
    uint32_t r;
    asm("cvt.rn.bf16x2.f32 %0, %1, %2;" : "=r"(r) : "f"(hi), "f"(lo));
    return r;
}
#define CP_ASYNC16(sm, gp) \
    asm volatile("cp.async.cg.shared.global [%0], [%1], 16;" :: "r"(sm), "l"(gp))
#define CP_COMMIT() asm volatile("cp.async.commit_group;" ::: "memory")
#define CP_WAIT2()  asm volatile("cp.async.wait_group 2;" ::: "memory")
#define CP_WAIT0()  asm volatile("cp.async.wait_group 0;" ::: "memory")
#define MMA_BF16(d, a, b) \
    asm volatile("mma.sync.aligned.m16n8k16.row.col.f32.bf16.bf16.f32 " \
        "{%0,%1,%2,%3}, {%4,%5,%6,%7}, {%8,%9}, {%0,%1,%2,%3};" \
        : "+f"((d)[0]), "+f"((d)[1]), "+f"((d)[2]), "+f"((d)[3]) \
        : "r"((a)[0]), "r"((a)[1]), "r"((a)[2]), "r"((a)[3]), \
          "r"((b)[0]), "r"((b)[1]))

// ---------------------------------------------------------------------------
// 1) Fused pack kernel.
//    Blocks [0, 8192): pool (16x16 -> 8x8) + transposed fNraw write +
//                      bf16 A-frag pack + row-sumsq partials.
//    Blocks [8192, 10240): B fragment pack + protoT + column-sumsq partials.
// ---------------------------------------------------------------------------
__global__ void pack_kernel(const float* __restrict__ x,
                            const float* __restrict__ proto) {
    __shared__ float sp[16][72];
    __shared__ float sq[8][8];
    int t = threadIdx.x;
    if (blockIdx.x < 8192) {
        // ---- pool + A pack ----
        int blk = blockIdx.x;
        int kq = blk & 127;
        int b = blk >> 7;
#pragma unroll
        for (int i = 0; i < 2; ++i) {
            int u = t + i * 256;            // 0..511
            int cl = u >> 5;                 // 0..15
            int m2 = (u & 31) * 2;
            int c = kq * 16 + cl;
            int ii = m2 >> 3, j = m2 & 7;    // j even
            const float* xp = x + ((size_t)(b * CC + c)) * 256;
            float4 r0 = *(const float4*)&xp[(2 * ii) * 16 + 2 * j];
            float4 r1 = *(const float4*)&xp[(2 * ii + 1) * 16 + 2 * j];
            sp[cl][m2]     = 0.25f * ((r0.x + r0.y) + (r1.x + r1.y));
            sp[cl][m2 + 1] = 0.25f * ((r0.z + r0.w) + (r1.z + r1.w));
        }
        __syncthreads();
        // transposed write: fNraw[b][m][kq*16 + c]
        {
            int m = t >> 2, c4 = (t & 3) * 4;
            float4 o = make_float4(sp[c4][m], sp[c4 + 1][m], sp[c4 + 2][m], sp[c4 + 3][m]);
            *(float4*)&g_fNraw[((size_t)(b * 64 + m)) * CC + kq * 16 + c4] = o;
        }
        // row sumsq partial for this kq chunk
        if (t < 64) {
            float s = 0.f;
#pragma unroll
            for (int cl = 0; cl < 16; ++cl) {
                float v = sp[cl][t];
                s += v * v;
            }
            g_npart[kq][b * 64 + t] = s;
        }
        // A fragment pack (hi/lo split)
        int h = t >> 7;        // 0: hi, 1: lo
        int q = t & 127;
        int f = q >> 5, lane = q & 31;
        int g = lane >> 2, tig = lane & 3;
        int m = f * 16 + g;
        float vals[8];
        vals[0] = sp[2 * tig][m];       vals[1] = sp[2 * tig + 1][m];
        vals[2] = sp[2 * tig][m + 8];   vals[3] = sp[2 * tig + 1][m + 8];
        vals[4] = sp[2 * tig + 8][m];     vals[5] = sp[2 * tig + 9][m];
        vals[6] = sp[2 * tig + 8][m + 8]; vals[7] = sp[2 * tig + 9][m + 8];
        uint32_t out[4];
#pragma unroll
        for (int r = 0; r < 4; ++r) {
            float e = vals[2 * r], o = vals[2 * r + 1];
            if (h == 0) out[r] = pack_bf(e, o);
            else        out[r] = pack_bf(e - bfh(e), o - bfh(o));
        }
        size_t idx = (((size_t)(b * 4 + f) * 128 + kq) * 32 + lane) * 4;
        if (h == 0) *(uint4*)&g_Ah[idx] = make_uint4(out[0], out[1], out[2], out[3]);
        else        *(uint4*)&g_Al[idx] = make_uint4(out[0], out[1], out[2], out[3]);
    } else {
        // ---- B pack + col sumsq ----
        int bx = blockIdx.x - 8192;                // 0..2047
        int gt = bx * 256 + t;                     // 0 .. 524287
        int lane = gt & 31;
        int frag = gt >> 5;                         // nt*128 + kq
        int kq = frag & 127, nt = frag >> 7;
        int g = lane >> 2, tig = lane & 3;
        int p = nt * 8 + g;
        int kb = kq * 16;
        float v0 = 0.f, v1 = 0.f, v2 = 0.f, v3 = 0.f;
        if (p < PP) {
            v0 = proto[(size_t)(kb + 2 * tig) * PP + p];
            v1 = proto[(size_t)(kb + 2 * tig + 1) * PP + p];
            v2 = proto[(size_t)(kb + 2 * tig + 8) * PP + p];
            v3 = proto[(size_t)(kb + 2 * tig + 9) * PP + p];
        }
        uint32_t b0h = pack_bf(v0, v1), b1h = pack_bf(v2, v3);
        uint32_t b0l = pack_bf(v0 - bfh(v0), v1 - bfh(v1));
        uint32_t b1l = pack_bf(v2 - bfh(v2), v3 - bfh(v3));
        size_t o = (size_t)frag * 64 + lane * 2;
        *(uint2*)&g_Bh[o] = make_uint2(b0h, b1h);
        *(uint2*)&g_Bl[o] = make_uint2(b0l, b1l);
        if (p < PP) {
            g_protoT[(size_t)p * CC + kb + 2 * tig]     = v0;
            g_protoT[(size_t)p * CC + kb + 2 * tig + 1] = v1;
            g_protoT[(size_t)p * CC + kb + 2 * tig + 8] = v2;
            g_protoT[(size_t)p * CC + kb + 2 * tig + 9] = v3;
        }
        float ss = v0 * v0 + v1 * v1 + v2 * v2 + v3 * v3;
        ss += __shfl_xor_sync(0xffffffffu, ss, 1);
        ss += __shfl_xor_sync(0xffffffffu, ss, 2);
        int wloc = t >> 5;
        if (tig == 0) sq[wloc][g] = ss;
        __syncthreads();
        if (t < 8) {
            float s = 0.f;
#pragma unroll
            for (int w2 = 0; w2 < 8; ++w2) s += sq[w2][t];
            int ntb = (bx * 8) >> 7;
            int chunk = bx & 15;
            g_cpart2[chunk][ntb * 8 + t] = s;
        }
    }
}

// ---------------------------------------------------------------------------
// 2) Row-norm finalize + zero-init of out[] accumulator segment
// ---------------------------------------------------------------------------
__global__ void normfin_kernel(float* __restrict__ dout) {
    int r = blockIdx.x * 256 + threadIdx.x;    // 0..4095
    float s = 0.f;
#pragma unroll 8
    for (int kq = 0; kq < 128; ++kq) s += g_npart[kq][r];
    float s1 = sqrtf(s);
    float r1 = 1.f / fmaxf(s1, 1e-12f);
    float na = s1 * r1 + 1e-3f;
    g_inv_norm[r] = r1;
    g_row_scale[r] = r1 / na;
    // zero out[0..6400) for the mma epilogue's atomic accumulation
    dout[OFF_OUT + r] = 0.f;
    if (r < 6400 - 4096) dout[OFF_OUT + 4096 + r] = 0.f;
}

// ---------------------------------------------------------------------------
// 3) bf16 3-split mma.sync GEMM + full fused epilogue (incl. out[] atomics).
//    Tile 128 rows (2 b) x 64 p, grid 16x32 = 512 CTAs, 2 CTAs/SM.
//    4-stage k32 ring, ONE __syncthreads per kt, loads issued before compute.
//    Stage = 24KB: Ah[0,8K) Al[8K,16K) Bh[16K,20K) Bl[20K,24K).
// ---------------------------------------------------------------------------
#define STAGE 24576
#define SSTR 129
__global__ __launch_bounds__(256, 2) void mma_kernel(const float* __restrict__ wgt,
                                                     const float* __restrict__ wgte,
                                                     float* __restrict__ dout) {
    extern __shared__ char smem[];
    uint32_t sb = smem_u32(smem);
    int t = threadIdx.x;
    int lane = t & 31, w = t >> 5;
    int wm = w & 1, wn = w >> 1;
    int mt0 = blockIdx.y * 8;
    int nt0 = blockIdx.x * 8;

    float acc[4][2][4];
#pragma unroll
    for (int i = 0; i < 4; ++i)
#pragma unroll
        for (int j = 0; j < 2; ++j)
#pragma unroll
            for (int q = 0; q < 4; ++q) acc[i][j][q] = 0.f;

    auto load_stage = [&](int sbuf, int kt) {
        uint32_t st = sb + sbuf * STAGE;
        int k0q = kt * 2;
#pragma unroll
        for (int i = 0; i < 2; ++i) {
            int q = t + i * 256;               // 0..511
            int frag = q >> 5, off = q & 31;   // frag = kq2*8 + mtl
            int kq2 = frag >> 3, mtl = frag & 7;
            size_t gidx = (((size_t)(mt0 + mtl) * 128) + k0q + kq2) * 128 + off * 4;
            CP_ASYNC16(st + frag * 512 + off * 16, g_Ah + gidx);
            CP_ASYNC16(st + 8192 + frag * 512 + off * 16, g_Al + gidx);
        }
        {
            int frag = t >> 4, off = t & 15;   // frag = kq2*8 + ntl
            int kq2 = frag >> 3, ntl = frag & 7;
            size_t gidx = (((size_t)(nt0 + ntl) * 128) + k0q + kq2) * 64 + off * 4;
            CP_ASYNC16(st + 16384 + frag * 256 + off * 16, g_Bh + gidx);
            CP_ASYNC16(st + 20480 + frag * 256 + off * 16, g_Bl + gidx);
        }
    };

    load_stage(0, 0); CP_COMMIT();
    load_stage(1, 1); CP_COMMIT();
    load_stage(2, 2); CP_COMMIT();

    for (int kt = 0; kt < 64; ++kt) {
        CP_WAIT2();             // stage kt resident
        __syncthreads();        // all warps done with stage kt-1 (refill target)
        if (kt < 61) load_stage((kt + 3) & 3, kt + 3);   // refill (kt-1)'s slot
        uint32_t st = sb + (kt & 3) * STAGE;
#pragma unroll
        for (int kq2 = 0; kq2 < 2; ++kq2) {
            uint32_t bh[2][2], bl[2][2];
#pragma unroll
            for (int nt = 0; nt < 2; ++nt) {
                uint32_t bo = st + 16384 + (uint32_t)((kq2 * 8 + wn * 2 + nt) * 32 + lane) * 8;
                asm("ld.shared.v2.b32 {%0,%1}, [%2];"
                    : "=r"(bh[nt][0]), "=r"(bh[nt][1]) : "r"(bo));
                asm("ld.shared.v2.b32 {%0,%1}, [%2];"
                    : "=r"(bl[nt][0]), "=r"(bl[nt][1]) : "r"(bo + 4096));
            }
#pragma unroll
            for (int mt = 0; mt < 4; ++mt) {
                uint32_t ah[4], al[4];
                uint32_t ao = st + (uint32_t)((kq2 * 8 + wm * 4 + mt) * 32 + lane) * 16;
                asm("ld.shared.v4.b32 {%0,%1,%2,%3}, [%4];"
                    : "=r"(ah[0]), "=r"(ah[1]), "=r"(ah[2]), "=r"(ah[3]) : "r"(ao));
                asm("ld.shared.v4.b32 {%0,%1,%2,%3}, [%4];"
                    : "=r"(al[0]), "=r"(al[1]), "=r"(al[2]), "=r"(al[3]) : "r"(ao + 8192));
#pragma unroll
                for (int nt = 0; nt < 2; ++nt) {
                    MMA_BF16(acc[mt][nt], ah, bh[nt]);
                    MMA_BF16(acc[mt][nt], ah, bl[nt]);
                    MMA_BF16(acc[mt][nt], al, bh[nt]);
                }
            }
        }
        CP_COMMIT();
    }
    CP_WAIT0();
    __syncthreads();

    // ---- epilogue ----
    float* S   = (float*)smem;                  // [64][SSTR]
    float* scs = S + 64 * SSTR;                 // col_scale [64]
    float* srs = scs + 64;                      // row_scale [128]
    int p0 = blockIdx.x * 64;
    int b0 = blockIdx.y * 2;
    if (t < 64) {
        int p = p0 + t;
        float s = 0.f;
#pragma unroll
        for (int ch = 0; ch < 16; ++ch) s += g_cpart2[ch][p];
        float s1 = sqrtf(s);
        float r1 = 1.f / fmaxf(s1, 1e-12f);
        scs[t] = r1 / (s1 * r1 + 1e-3f);
    } else if (t >= 128) {
        srs[t - 128] = g_row_scale[b0 * 64 + (t - 128)];
    }
    __syncthreads();

    int g = lane >> 2, tig = lane & 3;
#pragma unroll
    for (int mt = 0; mt < 4; ++mt) {
        int ml0 = (wm * 4 + mt) * 16 + g;
#pragma unroll
        for (int nt = 0; nt < 2; ++nt) {
            int pl = (wn * 2 + nt) * 8 + tig * 2;
            S[pl * SSTR + ml0]           = acc[mt][nt][0] * srs[ml0] * scs[pl];
            S[(pl + 1) * SSTR + ml0]     = acc[mt][nt][1] * srs[ml0] * scs[pl + 1];
            S[pl * SSTR + ml0 + 8]       = acc[mt][nt][2] * srs[ml0 + 8] * scs[pl];
            S[(pl + 1) * SSTR + ml0 + 8] = acc[mt][nt][3] * srs[ml0 + 8] * scs[pl + 1];
        }
    }
    __syncthreads();

    // per-warp: 8 p-columns, 2 batches each
#pragma unroll 1
    for (int i = 0; i < 8; ++i) {
        int pl = w * 8 + i;
        int p = p0 + pl;
        if (p >= PP) continue;
        float cs = scs[pl];
#pragma unroll 1
        for (int bhh = 0; bhh < 2; ++bhh) {
            int b = b0 + bhh;
            float v0 = S[pl * SSTR + bhh * 64 + lane];
            float v1 = S[pl * SSTR + bhh * 64 + 32 + lane];
            size_t obase = ((size_t)b * 1000 + p) * 64 + lane;
            __stcs(&dout[OFF_COSV + obase], v0);
            __stcs(&dout[OFF_COSV + obase + 32], v1);
            __stcs(&dout[OFF_COSD + obase], 1.f - v0);
            __stcs(&dout[OFF_COSD + obase + 32], 1.f - v1);

            float val; int idx;
            if (v1 > v0) { val = v1; idx = lane + 32; } else { val = v0; idx = lane; }
#pragma unroll
            for (int off = 16; off; off >>= 1) {
                float ov = __shfl_down_sync(0xffffffffu, val, off);
                int   oi = __shfl_down_sync(0xffffffffu, idx, off);
                if (ov > val || (ov == val && oi < idx)) { val = ov; idx = oi; }
            }
            val = __shfl_sync(0xffffffffu, val, 0);
            idx = __shfl_sync(0xffffffffu, idx, 0);

            float thr = val - EPS_TIE;
            unsigned mk0 = __ballot_sync(0xffffffffu, v0 >= thr);
            unsigned mk1 = __ballot_sync(0xffffffffu, v1 >= thr);
            if (__popc(mk0) + __popc(mk1) > 1) {
                const float* pt = g_protoT + (size_t)p * CC;
                float best = -3e38f; int bidx = 0;
                unsigned rem0 = mk0, rem1 = mk1;
                while (rem0 | rem1) {
                    int m;
                    if (rem0) { m = __ffs(rem0) - 1; rem0 &= rem0 - 1; }
                    else      { m = __ffs(rem1) + 31; rem1 &= rem1 - 1; }
                    const float* fn = g_fNraw + ((size_t)(b * 64 + m)) * CC;
                    float s = 0.f;
                    for (int c = lane * 4; c < CC; c += 128) {
                        float4 a = *(const float4*)&fn[c];
                        float4 qq = *(const float4*)&pt[c];
                        s += a.x * qq.x + a.y * qq.y + a.z * qq.z + a.w * qq.w;
                    }
#pragma unroll
                    for (int off = 16; off; off >>= 1)
                        s += __shfl_xor_sync(0xffffffffu, s, off);
                    float ev = s * srs[bhh * 64 + m] * cs;
                    if (ev > best) { best = ev; bidx = m; }
                }
                val = best;
                idx = bidx;
            }

            if (lane == 0) {
                int pair = b * 1000 + p;
                dout[OFF_SIM + pair] = val;
                float ww = wgt[p], wee = wgte[p];
                float sg = 1.f / (1.f + expf(-wee));
                float contrib = val * ww * sg;
                dout[OFF_CONTRIB + pair] = contrib;
                dout[OFF_ARGMAX + pair] = (float)idx;
                atomicAdd(&dout[OFF_OUT + b * 100 + p / 10], contrib);
            }

            // maxfs gather: 8KB row, batched load-8 / store-8 for MLP
            float r1 = g_inv_norm[b * 64 + idx];
            const float4* src = (const float4*)g_fNraw + ((size_t)(b * 64 + idx)) * 512;
            float4* dst = (float4*)(dout + OFF_MAXFS) + ((size_t)(b * 1000 + p)) * 512;
#pragma unroll
            for (int half = 0; half < 2; ++half) {
                float4 vv[8];
#pragma unroll
                for (int it = 0; it < 8; ++it)
                    vv[it] = src[(half * 8 + it) * 32 + lane];
#pragma unroll
                for (int it = 0; it < 8; ++it) {
                    float4 v = vv[it];
                    v.x *= r1; v.y *= r1; v.z *= r1; v.w *= r1;
                    __stcs(&dst[(half * 8 + it) * 32 + lane], v);
                }
            }
        }
    }
}

// ---------------------------------------------------------------------------
extern "C" void kernel_launch(void* const* d_in, const int* in_sizes, int n_in,
                              void* d_out, int out_size) {
    const float* x     = (const float*)d_in[0];
    const float* proto = (const float*)d_in[1];
    const float* w     = (const float*)d_in[2];
    const float* we    = (const float*)d_in[3];
    float* out = (float*)d_out;

    cudaFuncSetAttribute(mma_kernel, cudaFuncAttributeMaxDynamicSharedMemorySize, 4 * STAGE);

    pack_kernel<<<10240, 256>>>(x, proto);
    normfin_kernel<<<16, 256>>>(out);
    mma_kernel<<<dim3(16, 32), 256, 4 * STAGE>>>(w, we, out);
}